// round 10
// baseline (speedup 1.0000x reference)
#include <cuda_runtime.h>
#include <cstdint>

// ---------------------------------------------------------------------------
// out[524288,128] = X @ (sum_r s_r W_r).  mma.sync tf32, persistent CTAs.
// 16 warps (4M x 4N).  B fragments: ki 0..7 in registers, ki 8..15 in smem.
// W-fragment image computed in-kernel (no separate prep launch).
// ---------------------------------------------------------------------------
#define NREL 16
#define D 128
#define NNODES 524288

#define BM 128
#define XSTRIDE 132                 // smem row stride in floats (conflict-free A pattern)
#define TILES (NNODES / BM)         // 4096
#define GRID 148                    // persistent: 1 CTA/SM, 27-28 tiles each
#define NTHREADS 512

__device__ __forceinline__ uint32_t f2tf32(float f) {
    uint32_t r;
    asm("cvt.rna.tf32.f32 %0, %1;" : "=r"(r) : "f"(f));
    return r;
}

__device__ __forceinline__ void cp_async16(void* dst_smem, const void* src) {
    uint32_t d = (uint32_t)__cvta_generic_to_shared(dst_smem);
    asm volatile("cp.async.cg.shared.global [%0], [%1], 16;" :: "r"(d), "l"(src));
}
__device__ __forceinline__ void cp_commit() { asm volatile("cp.async.commit_group;"); }
template <int N>
__device__ __forceinline__ void cp_wait() {
    asm volatile("cp.async.wait_group %0;" :: "n"(N));
}

__device__ __forceinline__ void mma_tf32(float* c, const uint32_t* a, uint32_t b0, uint32_t b1) {
    asm volatile(
        "mma.sync.aligned.m16n8k8.row.col.f32.tf32.tf32.f32 "
        "{%0,%1,%2,%3}, {%4,%5,%6,%7}, {%8,%9}, {%0,%1,%2,%3};\n"
        : "+f"(c[0]), "+f"(c[1]), "+f"(c[2]), "+f"(c[3])
        : "r"(a[0]), "r"(a[1]), "r"(a[2]), "r"(a[3]), "r"(b0), "r"(b1));
}

// ---------------------------------------------------------------------------
// X tile loader: coalesced gmem -> padded smem (512 threads, 8 x 16B each)
// ---------------------------------------------------------------------------
__device__ __forceinline__ void load_x_tile(const float* __restrict__ gx,
                                            float* __restrict__ dst, int tid) {
#pragma unroll
    for (int i = 0; i < 8; i++) {
        int c   = tid + i * NTHREADS;   // 16B chunk id 0..4095
        int row = c >> 5;
        int cc  = c & 31;
        cp_async16(dst + row * XSTRIDE + cc * 4, gx + row * D + cc * 4);
    }
    cp_commit();
}

// ---------------------------------------------------------------------------
// Persistent GEMM kernel (prep fused into prologue)
// ---------------------------------------------------------------------------
__global__ void __launch_bounds__(NTHREADS, 1)
gemm_kernel(const float* __restrict__ X, const float* __restrict__ W,
            const float* __restrict__ s, float* __restrict__ Y) {
    extern __shared__ float smem[];
    float2* sw = (float2*)smem;          // 8192 float2 = 64 KB W fragments
    float*  sx = smem + 16384;           // 2 x [128][132] X buffers

    const int tid  = threadIdx.x;
    const int warp = tid >> 5;
    const int lane = tid & 31;
    const int wm   = warp >> 2;          // 0..3  (M groups of 32 rows)
    const int wn   = warp & 3;           // 0..3  (N groups of 32 cols)
    const int bid  = blockIdx.x;

    // Start first X tile immediately (overlaps W computation below)
    load_x_tile(X + (size_t)bid * BM * D, sx, tid);    // group 0

    // --- Compute W_eff fragments into smem (B-fragment layout) ------------
    // index ((ki*16 + n8)*32 + lane) -> float2 {b0, b1}
    //   b0 = W_eff[ki*8 + lane%4    ][n8*8 + lane/4]
    //   b1 = W_eff[ki*8 + lane%4 + 4][n8*8 + lane/4]
    {
        float sc[NREL];
#pragma unroll
        for (int r = 0; r < NREL; r++) sc[r] = s[r];
#pragma unroll
        for (int t = 0; t < 16; t++) {
            int idx  = tid + t * NTHREADS;   // 0..8191
            int l    = idx & 31;
            int n8   = (idx >> 5) & 15;
            int ki   = idx >> 9;
            int k0   = ki * 8 + (l & 3);
            int n    = n8 * 8 + (l >> 2);
            float b0 = 0.f, b1 = 0.f;
#pragma unroll
            for (int r = 0; r < NREL; r++) {
                b0 = fmaf(sc[r], W[(r * D + k0) * D + n], b0);
                b1 = fmaf(sc[r], W[(r * D + k0 + 4) * D + n], b1);
            }
            float2 v;
            v.x = __uint_as_float(f2tf32(b0));
            v.y = __uint_as_float(f2tf32(b1));
            sw[idx] = v;
        }
    }
    __syncthreads();   // W fragments visible to all warps

    // --- This warp's B fragments for ki = 0..7 into registers -------------
    uint32_t brx[8][4], bry[8][4];
#pragma unroll
    for (int ki = 0; ki < 8; ki++)
#pragma unroll
        for (int nf = 0; nf < 4; nf++) {
            float2 v = sw[(ki * 16 + wn * 4 + nf) * 32 + lane];
            brx[ki][nf] = __float_as_uint(v.x);
            bry[ki][nf] = __float_as_uint(v.y);
        }

    int tile = bid;
    int buf = 0;
    for (; tile < TILES; tile += GRID) {
        int next = tile + GRID;
        if (next < TILES) {
            load_x_tile(X + (size_t)next * BM * D, sx + (buf ^ 1) * (BM * XSTRIDE), tid);
            cp_wait<1>();                // current tile landed
        } else {
            cp_wait<0>();
        }
        __syncthreads();

        const float* xb = sx + buf * (BM * XSTRIDE);

        float acc[2][4][4];              // [mf][nf][quad]
#pragma unroll
        for (int mf = 0; mf < 2; mf++)
#pragma unroll
            for (int nf = 0; nf < 4; nf++)
#pragma unroll
                for (int q = 0; q < 4; q++) acc[mf][nf][q] = 0.f;

        // ki 0..7: B from registers
#pragma unroll
        for (int ki = 0; ki < 8; ki++) {
            uint32_t a[2][4];
#pragma unroll
            for (int mf = 0; mf < 2; mf++) {
                const float* ap = xb + (wm * 32 + mf * 16 + (lane >> 2)) * XSTRIDE
                                     + ki * 8 + (lane & 3);
                a[mf][0] = f2tf32(ap[0]);
                a[mf][1] = f2tf32(ap[8 * XSTRIDE]);
                a[mf][2] = f2tf32(ap[4]);
                a[mf][3] = f2tf32(ap[8 * XSTRIDE + 4]);
            }
#pragma unroll
            for (int nf = 0; nf < 4; nf++)
#pragma unroll
                for (int mf = 0; mf < 2; mf++)
                    mma_tf32(acc[mf][nf], a[mf], brx[ki][nf], bry[ki][nf]);
        }
        // ki 8..15: B from smem
#pragma unroll
        for (int ki = 8; ki < 16; ki++) {
            uint32_t a[2][4];
#pragma unroll
            for (int mf = 0; mf < 2; mf++) {
                const float* ap = xb + (wm * 32 + mf * 16 + (lane >> 2)) * XSTRIDE
                                     + ki * 8 + (lane & 3);
                a[mf][0] = f2tf32(ap[0]);
                a[mf][1] = f2tf32(ap[8 * XSTRIDE]);
                a[mf][2] = f2tf32(ap[4]);
                a[mf][3] = f2tf32(ap[8 * XSTRIDE + 4]);
            }
#pragma unroll
            for (int nf = 0; nf < 4; nf++) {
                float2 b = sw[(ki * 16 + wn * 4 + nf) * 32 + lane];
                uint32_t b0 = __float_as_uint(b.x);
                uint32_t b1 = __float_as_uint(b.y);
#pragma unroll
                for (int mf = 0; mf < 2; mf++)
                    mma_tf32(acc[mf][nf], a[mf], b0, b1);
            }
        }

        // Epilogue: STG.64, full 32B sectors
        float* yp = Y + (size_t)tile * BM * D;
#pragma unroll
        for (int mf = 0; mf < 2; mf++) {
            int row0 = wm * 32 + mf * 16 + (lane >> 2);
#pragma unroll
            for (int nf = 0; nf < 4; nf++) {
                int col = wn * 32 + nf * 8 + 2 * (lane & 3);
                float2 v0 = make_float2(acc[mf][nf][0], acc[mf][nf][1]);
                float2 v1 = make_float2(acc[mf][nf][2], acc[mf][nf][3]);
                *(float2*)(yp + (size_t)row0 * D + col)       = v0;
                *(float2*)(yp + (size_t)(row0 + 8) * D + col) = v1;
            }
        }
        __syncthreads();   // protect buf from next iteration's prefetch
        buf ^= 1;
    }
}

// ---------------------------------------------------------------------------
extern "C" void kernel_launch(void* const* d_in, const int* in_sizes, int n_in,
                              void* d_out, int out_size) {
    const float* X = (const float*)d_in[0];  // [524288, 128]
    const float* W = (const float*)d_in[1];  // [16, 128, 128]
    const float* s = (const float*)d_in[2];  // [16, 1]
    float* Y = (float*)d_out;                // [524288, 128]

    size_t smem_bytes = (16384 + 2 * BM * XSTRIDE) * sizeof(float);  // ~196 KB
    cudaFuncSetAttribute(gemm_kernel, cudaFuncAttributeMaxDynamicSharedMemorySize,
                         (int)smem_bytes);
    gemm_kernel<<<GRID, NTHREADS, smem_bytes>>>(X, W, s, Y);
}

// round 11
// speedup vs baseline: 1.1800x; 1.1800x over previous
#include <cuda_runtime.h>
#include <cstdint>

// ---------------------------------------------------------------------------
// out[524288,128] = X @ (sum_r s_r W_r).  mma.sync tf32.
// R5 base (8 warps, 4M x 2N, double-buffered X) +
//   - acc ping-pong: STG of tile i-1 issued before MMAs of tile i (overlap)
//   - B fragments packed as float4 pairs -> LDS.128 (half the B instructions)
// ---------------------------------------------------------------------------
#define NREL 16
#define D 128
#define NNODES 524288

#define BM 128
#define XSTRIDE 132                 // smem row stride in floats (conflict-free A pattern)
#define TILES (NNODES / BM)         // 4096
#define GRID 592                    // 4 waves on 148 SMs (best measured schedule)
#define NTHREADS 256

// W_eff in paired m16n8k8 tf32 B-fragment layout:
// entry ((ki*8 + q)*32 + lane) -> float4 {b0(n8=2q), b1(2q), b0(2q+1), b1(2q+1)}
//   b0(n8) = W_eff[ki*8 + lane%4    ][n8*8 + lane/4]
//   b1(n8) = W_eff[ki*8 + lane%4 + 4][n8*8 + lane/4]
__device__ float4 g_wfrag4[16 * 8 * 32];

__device__ __forceinline__ uint32_t f2tf32(float f) {
    uint32_t r;
    asm("cvt.rna.tf32.f32 %0, %1;" : "=r"(r) : "f"(f));
    return r;
}

__device__ __forceinline__ void cp_async16(void* dst_smem, const void* src) {
    uint32_t d = (uint32_t)__cvta_generic_to_shared(dst_smem);
    asm volatile("cp.async.cg.shared.global [%0], [%1], 16;" :: "r"(d), "l"(src));
}
__device__ __forceinline__ void cp_commit() { asm volatile("cp.async.commit_group;"); }
template <int N>
__device__ __forceinline__ void cp_wait() {
    asm volatile("cp.async.wait_group %0;" :: "n"(N));
}

__device__ __forceinline__ void mma_tf32(float* c, const uint32_t* a, uint32_t b0, uint32_t b1) {
    asm volatile(
        "mma.sync.aligned.m16n8k8.row.col.f32.tf32.tf32.f32 "
        "{%0,%1,%2,%3}, {%4,%5,%6,%7}, {%8,%9}, {%0,%1,%2,%3};\n"
        : "+f"(c[0]), "+f"(c[1]), "+f"(c[2]), "+f"(c[3])
        : "r"(a[0]), "r"(a[1]), "r"(a[2]), "r"(a[3]), "r"(b0), "r"(b1));
}

// ---------------------------------------------------------------------------
// Kernel 1: fold relations -> W_eff, tf32-round, store paired fragments
// ---------------------------------------------------------------------------
__global__ void prep_kernel(const float* __restrict__ W, const float* __restrict__ s) {
    int idx  = blockIdx.x * 256 + threadIdx.x;   // 0..4095
    int lane = idx & 31;
    int q    = (idx >> 5) & 7;
    int ki   = idx >> 8;

    int k0 = ki * 8 + (lane & 3);
    int n0 = (2 * q) * 8 + (lane >> 2);
    int n1 = n0 + 8;

    float x = 0.f, y = 0.f, z = 0.f, w = 0.f;
#pragma unroll
    for (int r = 0; r < NREL; r++) {
        float sc = s[r];
        x = fmaf(sc, W[(r * D + k0) * D + n0], x);
        y = fmaf(sc, W[(r * D + k0 + 4) * D + n0], y);
        z = fmaf(sc, W[(r * D + k0) * D + n1], z);
        w = fmaf(sc, W[(r * D + k0 + 4) * D + n1], w);
    }
    float4 v;
    v.x = __uint_as_float(f2tf32(x));
    v.y = __uint_as_float(f2tf32(y));
    v.z = __uint_as_float(f2tf32(z));
    v.w = __uint_as_float(f2tf32(w));
    g_wfrag4[idx] = v;
}

// ---------------------------------------------------------------------------
// X tile loader: coalesced gmem -> padded smem
// ---------------------------------------------------------------------------
__device__ __forceinline__ void load_x_tile(const float* __restrict__ gx,
                                            float* __restrict__ dst, int tid) {
#pragma unroll
    for (int i = 0; i < 16; i++) {
        int c   = tid + i * NTHREADS;   // 16B chunk id 0..4095
        int row = c >> 5;
        int cc  = c & 31;
        cp_async16(dst + row * XSTRIDE + cc * 4, gx + row * D + cc * 4);
    }
    cp_commit();
}

// ---------------------------------------------------------------------------
// Per-tile compute: full K, acc[2][8][4] (mf, nf, quad)
// ---------------------------------------------------------------------------
__device__ __forceinline__ void compute_tile(const float* __restrict__ xb,
                                             const float4* __restrict__ sw4,
                                             float acc[2][8][4],
                                             int wm, int wn, int lane) {
#pragma unroll
    for (int mf = 0; mf < 2; mf++)
#pragma unroll
        for (int nf = 0; nf < 8; nf++)
#pragma unroll
            for (int q = 0; q < 4; q++) acc[mf][nf][q] = 0.f;

#pragma unroll
    for (int ki = 0; ki < 16; ki++) {
        // A fragments (XSTRIDE=132 -> bank == laneid pattern, conflict-free)
        uint32_t a[2][4];
#pragma unroll
        for (int mf = 0; mf < 2; mf++) {
            const float* ap = xb + (wm * 32 + mf * 16 + (lane >> 2)) * XSTRIDE
                                 + ki * 8 + (lane & 3);
            a[mf][0] = f2tf32(ap[0]);
            a[mf][1] = f2tf32(ap[8 * XSTRIDE]);
            a[mf][2] = f2tf32(ap[4]);
            a[mf][3] = f2tf32(ap[8 * XSTRIDE + 4]);
        }
#pragma unroll
        for (int qq = 0; qq < 4; qq++) {
            float4 bv = sw4[(ki * 8 + wn * 4 + qq) * 32 + lane];   // LDS.128
            uint32_t b0a = __float_as_uint(bv.x), b1a = __float_as_uint(bv.y);
            uint32_t b0b = __float_as_uint(bv.z), b1b = __float_as_uint(bv.w);
#pragma unroll
            for (int mf = 0; mf < 2; mf++) {
                mma_tf32(acc[mf][2 * qq + 0], a[mf], b0a, b1a);
                mma_tf32(acc[mf][2 * qq + 1], a[mf], b0b, b1b);
            }
        }
    }
}

// ---------------------------------------------------------------------------
// Per-tile store: STG.64, full 32B sectors
// ---------------------------------------------------------------------------
__device__ __forceinline__ void store_tile(float* __restrict__ Y, int tile,
                                           const float acc[2][8][4],
                                           int wm, int wn, int lane) {
    float* yp = Y + (size_t)tile * BM * D;
#pragma unroll
    for (int mf = 0; mf < 2; mf++) {
        int row0 = wm * 32 + mf * 16 + (lane >> 2);
#pragma unroll
        for (int nf = 0; nf < 8; nf++) {
            int col = wn * 64 + nf * 8 + 2 * (lane & 3);
            float2 v0 = make_float2(acc[mf][nf][0], acc[mf][nf][1]);
            float2 v1 = make_float2(acc[mf][nf][2], acc[mf][nf][3]);
            *(float2*)(yp + (size_t)row0 * D + col)       = v0;
            *(float2*)(yp + (size_t)(row0 + 8) * D + col) = v1;
        }
    }
}

// ---------------------------------------------------------------------------
// Kernel 2: grid-stride GEMM, acc ping-pong across tile pairs
// ---------------------------------------------------------------------------
__global__ void __launch_bounds__(NTHREADS, 1)
gemm_kernel(const float* __restrict__ X, float* __restrict__ Y) {
    extern __shared__ float smem[];
    float4* sw4 = (float4*)smem;         // 4096 float4 = 64 KB W fragments
    float*  sx  = smem + 16384;          // 2 x [128][132] X buffers
    float*  bufA = sx;
    float*  bufB = sx + BM * XSTRIDE;

    const int tid  = threadIdx.x;
    const int warp = tid >> 5;
    const int lane = tid & 31;
    const int wm   = warp >> 1;          // 0..3  (M groups of 32 rows)
    const int wn   = warp & 1;           // 0..1  (N groups of 64 cols)

    // Stage W fragments into smem (cp.async group 0)
    {
        const float* gw = (const float*)g_wfrag4;
#pragma unroll
        for (int i = 0; i < 16; i++) {
            int c = tid + i * NTHREADS;  // 16B chunk 0..4095
            cp_async16(&smem[c * 4], gw + c * 4);
        }
    }
    cp_commit();

    int t = blockIdx.x;
    load_x_tile(X + (size_t)t * BM * D, bufA, tid);    // group 1

    float acc0[2][8][4], acc1[2][8][4];
    int pend0 = -1, pend1 = -1;

    for (;;) {
        // ---- slot A: tile t from bufA into acc0 --------------------------
        int t1 = t + GRID;
        if (t1 < TILES) { load_x_tile(X + (size_t)t1 * BM * D, bufB, tid); cp_wait<1>(); }
        else            { cp_wait<0>(); }
        __syncthreads();
        if (pend1 >= 0) { store_tile(Y, pend1, acc1, wm, wn, lane); pend1 = -1; }
        compute_tile(bufA, sw4, acc0, wm, wn, lane);
        pend0 = t;
        __syncthreads();
        if (t1 >= TILES) break;

        // ---- slot B: tile t1 from bufB into acc1 -------------------------
        int t2 = t1 + GRID;
        if (t2 < TILES) { load_x_tile(X + (size_t)t2 * BM * D, bufA, tid); cp_wait<1>(); }
        else            { cp_wait<0>(); }
        __syncthreads();
        if (pend0 >= 0) { store_tile(Y, pend0, acc0, wm, wn, lane); pend0 = -1; }
        compute_tile(bufB, sw4, acc1, wm, wn, lane);
        pend1 = t1;
        __syncthreads();
        if (t2 >= TILES) break;
        t = t2;
    }
    if (pend0 >= 0) store_tile(Y, pend0, acc0, wm, wn, lane);
    if (pend1 >= 0) store_tile(Y, pend1, acc1, wm, wn, lane);
}

// ---------------------------------------------------------------------------
extern "C" void kernel_launch(void* const* d_in, const int* in_sizes, int n_in,
                              void* d_out, int out_size) {
    const float* X = (const float*)d_in[0];  // [524288, 128]
    const float* W = (const float*)d_in[1];  // [16, 128, 128]
    const float* s = (const float*)d_in[2];  // [16, 1]
    float* Y = (float*)d_out;                // [524288, 128]

    prep_kernel<<<16, 256>>>(W, s);

    size_t smem_bytes = (16384 + 2 * BM * XSTRIDE) * sizeof(float);  // ~196 KB
    cudaFuncSetAttribute(gemm_kernel, cudaFuncAttributeMaxDynamicSharedMemorySize,
                         (int)smem_bytes);
    gemm_kernel<<<GRID, NTHREADS, smem_bytes>>>(X, Y);
}

// round 13
// speedup vs baseline: 1.2603x; 1.0680x over previous
#include <cuda_runtime.h>
#include <cstdint>

// ---------------------------------------------------------------------------
// out[524288,128] = X @ (sum_r s_r W_r).  mma.sync tf32.
// R5/R11 compute structure (8 warps, 4M x 2N, XSTRIDE=132, paired-B LDS.128)
// with ALL smem fills converted from per-16B cp.async (LSU-issue bound:
// 4096 ops x rt8 = 8192 cyc/tile) to cp.async.bulk + mbarrier (128 ops/tile).
// ---------------------------------------------------------------------------
#define NREL 16
#define D 128
#define NNODES 524288

#define BM 128
#define XSTRIDE 132                 // smem row stride in floats (conflict-free A pattern)
#define XBUF_BYTES (BM * XSTRIDE * 4)   // 67584
#define TILES (NNODES / BM)         // 4096
#define GRID 592                    // 4 waves on 148 SMs
#define NTHREADS 256

// smem layout (byte offsets)
#define SM_MBAR_W 0
#define SM_MBAR0  8
#define SM_MBAR1  16
#define SM_W      1024              // 64 KB W fragments
#define SM_X0     (SM_W + 65536)
#define SM_X1     (SM_X0 + XBUF_BYTES)
#define SM_TOTAL  (SM_X1 + XBUF_BYTES)   // 201728 bytes

// W_eff in paired m16n8k8 tf32 B-fragment layout:
// entry ((ki*8 + q)*32 + lane) -> float4 {b0(n8=2q), b1(2q), b0(2q+1), b1(2q+1)}
__device__ float4 g_wfrag4[16 * 8 * 32];

__device__ __forceinline__ uint32_t smem_u32(const void* p) {
    uint32_t a;
    asm("{ .reg .u64 t; cvta.to.shared.u64 t, %1; cvt.u32.u64 %0, t; }" : "=r"(a) : "l"(p));
    return a;
}
__device__ __forceinline__ uint32_t f2tf32(float f) {
    uint32_t r;
    asm("cvt.rna.tf32.f32 %0, %1;" : "=r"(r) : "f"(f));
    return r;
}
__device__ __forceinline__ void bulk_ld(uint32_t dst, const void* src, uint32_t bytes,
                                        uint32_t mbar) {
    asm volatile(
        "cp.async.bulk.shared::cluster.global.mbarrier::complete_tx::bytes [%0], [%1], %2, [%3];"
        :: "r"(dst), "l"(src), "r"(bytes), "r"(mbar) : "memory");
}
#define MBAR_INIT(m, n) \
    asm volatile("mbarrier.init.shared.b64 [%0], %1;" :: "r"(m), "r"((uint32_t)(n)) : "memory")
#define MBAR_EXPECT(m, tx) \
    asm volatile("mbarrier.arrive.expect_tx.shared.b64 _, [%0], %1;" :: "r"(m), "r"((uint32_t)(tx)) : "memory")
#define MBAR_WAIT(m, parity) do {                                                \
    uint32_t _m = (m), _p = (parity), _d;                                        \
    asm volatile("{ .reg .pred p; mbarrier.try_wait.parity.acquire.cta.shared::cta.b64 p, [%1], %2; selp.b32 %0,1,0,p; }" \
                 : "=r"(_d) : "r"(_m), "r"(_p) : "memory");                      \
    if (!_d) {                                                                   \
        asm volatile("{ .reg .pred P1; WL_%=: mbarrier.try_wait.parity.acquire.cta.shared::cta.b64 P1, [%0], %1, 0x989680;" \
                     " @P1 bra.uni WD_%=; bra.uni WL_%=; WD_%=: }"               \
                     :: "r"(_m), "r"(_p) : "memory");                            \
    }                                                                            \
} while (0)

__device__ __forceinline__ void mma_tf32(float* c, const uint32_t* a, uint32_t b0, uint32_t b1) {
    asm volatile(
        "mma.sync.aligned.m16n8k8.row.col.f32.tf32.tf32.f32 "
        "{%0,%1,%2,%3}, {%4,%5,%6,%7}, {%8,%9}, {%0,%1,%2,%3};\n"
        : "+f"(c[0]), "+f"(c[1]), "+f"(c[2]), "+f"(c[3])
        : "r"(a[0]), "r"(a[1]), "r"(a[2]), "r"(a[3]), "r"(b0), "r"(b1));
}

// ---------------------------------------------------------------------------
// Kernel 1: fold relations -> W_eff, tf32-round, store paired fragments
// ---------------------------------------------------------------------------
__global__ void prep_kernel(const float* __restrict__ W, const float* __restrict__ s) {
    int idx  = blockIdx.x * 256 + threadIdx.x;   // 0..4095
    int lane = idx & 31;
    int q    = (idx >> 5) & 7;
    int ki   = idx >> 8;

    int k0 = ki * 8 + (lane & 3);
    int n0 = (2 * q) * 8 + (lane >> 2);
    int n1 = n0 + 8;

    float x = 0.f, y = 0.f, z = 0.f, w = 0.f;
#pragma unroll
    for (int r = 0; r < NREL; r++) {
        float sc = s[r];
        x = fmaf(sc, W[(r * D + k0) * D + n0], x);
        y = fmaf(sc, W[(r * D + k0 + 4) * D + n0], y);
        z = fmaf(sc, W[(r * D + k0) * D + n1], z);
        w = fmaf(sc, W[(r * D + k0 + 4) * D + n1], w);
    }
    float4 v;
    v.x = __uint_as_float(f2tf32(x));
    v.y = __uint_as_float(f2tf32(y));
    v.z = __uint_as_float(f2tf32(z));
    v.w = __uint_as_float(f2tf32(w));
    g_wfrag4[idx] = v;
}

// ---------------------------------------------------------------------------
// X tile loader: one 512B bulk per row (dst stride 528B keeps XSTRIDE pad)
// ---------------------------------------------------------------------------
__device__ __forceinline__ void load_x_bulk(const float* __restrict__ gx,
                                            uint32_t sdst, uint32_t mbar, int tid) {
    if (tid == 0) MBAR_EXPECT(mbar, BM * D * 4);           // 65536 bytes
    if (tid < BM) bulk_ld(sdst + tid * (XSTRIDE * 4), gx + (size_t)tid * D, D * 4, mbar);
}

// ---------------------------------------------------------------------------
// Per-tile compute: full K, acc[2][8][4] (mf, nf, quad)
// ---------------------------------------------------------------------------
__device__ __forceinline__ void compute_tile(const float* __restrict__ xb,
                                             const float4* __restrict__ sw4,
                                             float acc[2][8][4],
                                             int wm, int wn, int lane) {
#pragma unroll
    for (int mf = 0; mf < 2; mf++)
#pragma unroll
        for (int nf = 0; nf < 8; nf++)
#pragma unroll
            for (int q = 0; q < 4; q++) acc[mf][nf][q] = 0.f;

#pragma unroll
    for (int ki = 0; ki < 16; ki++) {
        uint32_t a[2][4];
#pragma unroll
        for (int mf = 0; mf < 2; mf++) {
            const float* ap = xb + (wm * 32 + mf * 16 + (lane >> 2)) * XSTRIDE
                                 + ki * 8 + (lane & 3);
            a[mf][0] = f2tf32(ap[0]);
            a[mf][1] = f2tf32(ap[8 * XSTRIDE]);
            a[mf][2] = f2tf32(ap[4]);
            a[mf][3] = f2tf32(ap[8 * XSTRIDE + 4]);
        }
#pragma unroll
        for (int qq = 0; qq < 4; qq++) {
            float4 bv = sw4[(ki * 8 + wn * 4 + qq) * 32 + lane];   // LDS.128
            uint32_t b0a = __float_as_uint(bv.x), b1a = __float_as_uint(bv.y);
            uint32_t b0b = __float_as_uint(bv.z), b1b = __float_as_uint(bv.w);
#pragma unroll
            for (int mf = 0; mf < 2; mf++) {
                mma_tf32(acc[mf][2 * qq + 0], a[mf], b0a, b1a);
                mma_tf32(acc[mf][2 * qq + 1], a[mf], b0b, b1b);
            }
        }
    }
}

__device__ __forceinline__ void store_tile(float* __restrict__ Y, int tile,
                                           const float acc[2][8][4],
                                           int wm, int wn, int lane) {
    float* yp = Y + (size_t)tile * BM * D;
#pragma unroll
    for (int mf = 0; mf < 2; mf++) {
        int row0 = wm * 32 + mf * 16 + (lane >> 2);
#pragma unroll
        for (int nf = 0; nf < 8; nf++) {
            int col = wn * 64 + nf * 8 + 2 * (lane & 3);
            float2 v0 = make_float2(acc[mf][nf][0], acc[mf][nf][1]);
            float2 v1 = make_float2(acc[mf][nf][2], acc[mf][nf][3]);
            *(float2*)(yp + (size_t)row0 * D + col)       = v0;
            *(float2*)(yp + (size_t)(row0 + 8) * D + col) = v1;
        }
    }
}

// ---------------------------------------------------------------------------
// Kernel 2: grid-stride GEMM, bulk-async double buffer
// ---------------------------------------------------------------------------
__global__ void __launch_bounds__(NTHREADS, 1)
gemm_kernel(const float* __restrict__ X, float* __restrict__ Y) {
    extern __shared__ char smem[];
    const uint32_t sbase = smem_u32(smem);
    const float4* sw4 = (const float4*)(smem + SM_W);

    const int tid  = threadIdx.x;
    const int warp = tid >> 5;
    const int lane = tid & 31;
    const int wm   = warp >> 1;          // 0..3  (M groups of 32 rows)
    const int wn   = warp & 1;           // 0..1  (N groups of 64 cols)

    if (tid == 0) {
        MBAR_INIT(sbase + SM_MBAR_W, 1);
        MBAR_INIT(sbase + SM_MBAR0, 1);
        MBAR_INIT(sbase + SM_MBAR1, 1);
    }
    __syncthreads();

    // Prologue: W (one 64KB bulk), X tile 0, X tile 1
    if (tid == 0) {
        MBAR_EXPECT(sbase + SM_MBAR_W, 65536);
        bulk_ld(sbase + SM_W, g_wfrag4, 65536, sbase + SM_MBAR_W);
    }
    int t0 = blockIdx.x;
    load_x_bulk(X + (size_t)t0 * BM * D, sbase + SM_X0, sbase + SM_MBAR0, tid);
    if (t0 + GRID < TILES)
        load_x_bulk(X + (size_t)(t0 + GRID) * BM * D, sbase + SM_X1, sbase + SM_MBAR1, tid);

    MBAR_WAIT(sbase + SM_MBAR_W, 0);     // W fragments ready

    int ph0 = 0, ph1 = 0;
    int buf = 0;
    float acc[2][8][4];

    for (int tile = t0; tile < TILES; tile += GRID) {
        uint32_t mbar = sbase + (buf ? SM_MBAR1 : SM_MBAR0);
        uint32_t xoff = buf ? SM_X1 : SM_X0;
        if (buf) { MBAR_WAIT(mbar, ph1); ph1 ^= 1; }
        else     { MBAR_WAIT(mbar, ph0); ph0 ^= 1; }

        compute_tile((const float*)(smem + xoff), sw4, acc, wm, wn, lane);
        __syncthreads();                 // all warps done reading this buffer

        int nn = tile + 2 * GRID;        // refill this buffer for tile+2
        if (nn < TILES)
            load_x_bulk(X + (size_t)nn * BM * D, sbase + xoff, mbar, tid);

        store_tile(Y, tile, acc, wm, wn, lane);   // overlaps the bulk in flight
        buf ^= 1;
    }
}

// ---------------------------------------------------------------------------
extern "C" void kernel_launch(void* const* d_in, const int* in_sizes, int n_in,
                              void* d_out, int out_size) {
    const float* X = (const float*)d_in[0];  // [524288, 128]
    const float* W = (const float*)d_in[1];  // [16, 128, 128]
    const float* s = (const float*)d_in[2];  // [16, 1]
    float* Y = (float*)d_out;                // [524288, 128]

    prep_kernel<<<16, 256>>>(W, s);

    cudaFuncSetAttribute(gemm_kernel, cudaFuncAttributeMaxDynamicSharedMemorySize,
                         SM_TOTAL);
    gemm_kernel<<<GRID, NTHREADS, SM_TOTAL>>>(X, Y);
}

// round 15
// speedup vs baseline: 1.3103x; 1.0397x over previous
#include <cuda_runtime.h>
#include <cstdint>

// ---------------------------------------------------------------------------
// out[524288,128] = X @ (sum_r s_r W_r).  mma.sync tf32.
// R13 structure (8 warps 4Mx2N, XSTRIDE=132, paired-B LDS.128, bulk-async X)
//  + software-pipelined ki loop (A/B regs double-buffered across ki)
//  + persistent GRID=148 (no wave transitions, one prologue per SM)
// ---------------------------------------------------------------------------
#define NREL 16
#define D 128
#define NNODES 524288

#define BM 128
#define XSTRIDE 132                 // smem row stride in floats (conflict-free A pattern)
#define XBUF_BYTES (BM * XSTRIDE * 4)   // 67584
#define TILES (NNODES / BM)         // 4096
#define GRID 148                    // persistent: 27-28 tiles per CTA
#define NTHREADS 256

// smem layout (byte offsets)
#define SM_MBAR_W 0
#define SM_MBAR0  8
#define SM_MBAR1  16
#define SM_W      1024              // 64 KB W fragments
#define SM_X0     (SM_W + 65536)
#define SM_X1     (SM_X0 + XBUF_BYTES)
#define SM_TOTAL  (SM_X1 + XBUF_BYTES)   // 201728 bytes

// W_eff in paired m16n8k8 tf32 B-fragment layout:
// entry ((ki*8 + q)*32 + lane) -> float4 {b0(n8=2q), b1(2q), b0(2q+1), b1(2q+1)}
__device__ float4 g_wfrag4[16 * 8 * 32];

__device__ __forceinline__ uint32_t smem_u32(const void* p) {
    uint32_t a;
    asm("{ .reg .u64 t; cvta.to.shared.u64 t, %1; cvt.u32.u64 %0, t; }" : "=r"(a) : "l"(p));
    return a;
}
__device__ __forceinline__ uint32_t f2tf32(float f) {
    uint32_t r;
    asm("cvt.rna.tf32.f32 %0, %1;" : "=r"(r) : "f"(f));
    return r;
}
__device__ __forceinline__ void bulk_ld(uint32_t dst, const void* src, uint32_t bytes,
                                        uint32_t mbar) {
    asm volatile(
        "cp.async.bulk.shared::cluster.global.mbarrier::complete_tx::bytes [%0], [%1], %2, [%3];"
        :: "r"(dst), "l"(src), "r"(bytes), "r"(mbar) : "memory");
}
#define MBAR_INIT(m, n) \
    asm volatile("mbarrier.init.shared.b64 [%0], %1;" :: "r"(m), "r"((uint32_t)(n)) : "memory")
#define MBAR_EXPECT(m, tx) \
    asm volatile("mbarrier.arrive.expect_tx.shared.b64 _, [%0], %1;" :: "r"(m), "r"((uint32_t)(tx)) : "memory")
#define MBAR_WAIT(m, parity) do {                                                \
    uint32_t _m = (m), _p = (parity), _d;                                        \
    asm volatile("{ .reg .pred p; mbarrier.try_wait.parity.acquire.cta.shared::cta.b64 p, [%1], %2; selp.b32 %0,1,0,p; }" \
                 : "=r"(_d) : "r"(_m), "r"(_p) : "memory");                      \
    if (!_d) {                                                                   \
        asm volatile("{ .reg .pred P1; WL_%=: mbarrier.try_wait.parity.acquire.cta.shared::cta.b64 P1, [%0], %1, 0x989680;" \
                     " @P1 bra.uni WD_%=; bra.uni WL_%=; WD_%=: }"               \
                     :: "r"(_m), "r"(_p) : "memory");                            \
    }                                                                            \
} while (0)

__device__ __forceinline__ void mma_tf32(float* c, const uint32_t* a, uint32_t b0, uint32_t b1) {
    asm volatile(
        "mma.sync.aligned.m16n8k8.row.col.f32.tf32.tf32.f32 "
        "{%0,%1,%2,%3}, {%4,%5,%6,%7}, {%8,%9}, {%0,%1,%2,%3};\n"
        : "+f"(c[0]), "+f"(c[1]), "+f"(c[2]), "+f"(c[3])
        : "r"(a[0]), "r"(a[1]), "r"(a[2]), "r"(a[3]), "r"(b0), "r"(b1));
}

// ---------------------------------------------------------------------------
// Kernel 1: fold relations -> W_eff, tf32-round, store paired fragments
// ---------------------------------------------------------------------------
__global__ void prep_kernel(const float* __restrict__ W, const float* __restrict__ s) {
    int idx  = blockIdx.x * 256 + threadIdx.x;   // 0..4095
    int lane = idx & 31;
    int q    = (idx >> 5) & 7;
    int ki   = idx >> 8;

    int k0 = ki * 8 + (lane & 3);
    int n0 = (2 * q) * 8 + (lane >> 2);
    int n1 = n0 + 8;

    float x = 0.f, y = 0.f, z = 0.f, w = 0.f;
#pragma unroll
    for (int r = 0; r < NREL; r++) {
        float sc = s[r];
        x = fmaf(sc, W[(r * D + k0) * D + n0], x);
        y = fmaf(sc, W[(r * D + k0 + 4) * D + n0], y);
        z = fmaf(sc, W[(r * D + k0) * D + n1], z);
        w = fmaf(sc, W[(r * D + k0 + 4) * D + n1], w);
    }
    float4 v;
    v.x = __uint_as_float(f2tf32(x));
    v.y = __uint_as_float(f2tf32(y));
    v.z = __uint_as_float(f2tf32(z));
    v.w = __uint_as_float(f2tf32(w));
    g_wfrag4[idx] = v;
}

// ---------------------------------------------------------------------------
// X tile loader: one 512B bulk per row (dst stride 528B keeps XSTRIDE pad)
// ---------------------------------------------------------------------------
__device__ __forceinline__ void load_x_bulk(const float* __restrict__ gx,
                                            uint32_t sdst, uint32_t mbar, int tid) {
    if (tid == 0) MBAR_EXPECT(mbar, BM * D * 4);           // 65536 bytes
    if (tid < BM) bulk_ld(sdst + tid * (XSTRIDE * 4), gx + (size_t)tid * D, D * 4, mbar);
}

// ---------------------------------------------------------------------------
// ki-step fragment loaders (regs)
// ---------------------------------------------------------------------------
__device__ __forceinline__ void load_a_frag(const float* __restrict__ xb,
                                            int wm, int lane, int ki, uint32_t a[2][4]) {
#pragma unroll
    for (int mf = 0; mf < 2; mf++) {
        const float* ap = xb + (wm * 32 + mf * 16 + (lane >> 2)) * XSTRIDE
                             + ki * 8 + (lane & 3);
        a[mf][0] = f2tf32(ap[0]);
        a[mf][1] = f2tf32(ap[8 * XSTRIDE]);
        a[mf][2] = f2tf32(ap[4]);
        a[mf][3] = f2tf32(ap[8 * XSTRIDE + 4]);
    }
}
__device__ __forceinline__ void load_b_frag(const float4* __restrict__ sw4,
                                            int wn, int lane, int ki, float4 bv[4]) {
#pragma unroll
    for (int qq = 0; qq < 4; qq++)
        bv[qq] = sw4[(ki * 8 + wn * 4 + qq) * 32 + lane];   // LDS.128
}
__device__ __forceinline__ void mma_step(float acc[2][8][4], uint32_t a[2][4], float4 bv[4]) {
#pragma unroll
    for (int qq = 0; qq < 4; qq++) {
        uint32_t b0a = __float_as_uint(bv[qq].x), b1a = __float_as_uint(bv[qq].y);
        uint32_t b0b = __float_as_uint(bv[qq].z), b1b = __float_as_uint(bv[qq].w);
#pragma unroll
        for (int mf = 0; mf < 2; mf++) {
            mma_tf32(acc[mf][2 * qq + 0], a[mf], b0a, b1a);
            mma_tf32(acc[mf][2 * qq + 1], a[mf], b0b, b1b);
        }
    }
}

// ---------------------------------------------------------------------------
// Per-tile compute: software-pipelined over ki (loads for ki+1 before MMAs of ki)
// ---------------------------------------------------------------------------
__device__ __forceinline__ void compute_tile(const float* __restrict__ xb,
                                             const float4* __restrict__ sw4,
                                             float acc[2][8][4],
                                             int wm, int wn, int lane) {
#pragma unroll
    for (int mf = 0; mf < 2; mf++)
#pragma unroll
        for (int nf = 0; nf < 8; nf++)
#pragma unroll
            for (int q = 0; q < 4; q++) acc[mf][nf][q] = 0.f;

    uint32_t a0[2][4], a1[2][4];
    float4   b0v[4],  b1v[4];
    load_a_frag(xb, wm, lane, 0, a0);
    load_b_frag(sw4, wn, lane, 0, b0v);

#pragma unroll
    for (int ki = 0; ki < 16; ki++) {
        if (ki + 1 < 16) {
            if (ki & 1) { load_a_frag(xb, wm, lane, ki + 1, a0);
                          load_b_frag(sw4, wn, lane, ki + 1, b0v); }
            else        { load_a_frag(xb, wm, lane, ki + 1, a1);
                          load_b_frag(sw4, wn, lane, ki + 1, b1v); }
        }
        if (ki & 1) mma_step(acc, a1, b1v);
        else        mma_step(acc, a0, b0v);
    }
}

__device__ __forceinline__ void store_tile(float* __restrict__ Y, int tile,
                                           const float acc[2][8][4],
                                           int wm, int wn, int lane) {
    float* yp = Y + (size_t)tile * BM * D;
#pragma unroll
    for (int mf = 0; mf < 2; mf++) {
        int row0 = wm * 32 + mf * 16 + (lane >> 2);
#pragma unroll
        for (int nf = 0; nf < 8; nf++) {
            int col = wn * 64 + nf * 8 + 2 * (lane & 3);
            float2 v0 = make_float2(acc[mf][nf][0], acc[mf][nf][1]);
            float2 v1 = make_float2(acc[mf][nf][2], acc[mf][nf][3]);
            *(float2*)(yp + (size_t)row0 * D + col)       = v0;
            *(float2*)(yp + (size_t)(row0 + 8) * D + col) = v1;
        }
    }
}

// ---------------------------------------------------------------------------
// Kernel 2: persistent grid-stride GEMM, bulk-async double buffer
// ---------------------------------------------------------------------------
__global__ void __launch_bounds__(NTHREADS, 1)
gemm_kernel(const float* __restrict__ X, float* __restrict__ Y) {
    extern __shared__ char smem[];
    const uint32_t sbase = smem_u32(smem);
    const float4* sw4 = (const float4*)(smem + SM_W);

    const int tid  = threadIdx.x;
    const int warp = tid >> 5;
    const int lane = tid & 31;
    const int wm   = warp >> 1;          // 0..3  (M groups of 32 rows)
    const int wn   = warp & 1;           // 0..1  (N groups of 64 cols)

    if (tid == 0) {
        MBAR_INIT(sbase + SM_MBAR_W, 1);
        MBAR_INIT(sbase + SM_MBAR0, 1);
        MBAR_INIT(sbase + SM_MBAR1, 1);
    }
    __syncthreads();

    // Prologue: W (one 64KB bulk), X tile 0, X tile 1
    if (tid == 0) {
        MBAR_EXPECT(sbase + SM_MBAR_W, 65536);
        bulk_ld(sbase + SM_W, g_wfrag4, 65536, sbase + SM_MBAR_W);
    }
    int t0 = blockIdx.x;
    load_x_bulk(X + (size_t)t0 * BM * D, sbase + SM_X0, sbase + SM_MBAR0, tid);
    if (t0 + GRID < TILES)
        load_x_bulk(X + (size_t)(t0 + GRID) * BM * D, sbase + SM_X1, sbase + SM_MBAR1, tid);

    MBAR_WAIT(sbase + SM_MBAR_W, 0);     // W fragments ready

    int ph0 = 0, ph1 = 0;
    int buf = 0;
    float acc[2][8][4];

    for (int tile = t0; tile < TILES; tile += GRID) {
        uint32_t mbar = sbase + (buf ? SM_MBAR1 : SM_MBAR0);
        uint32_t xoff = buf ? SM_X1 : SM_X0;
        if (buf) { MBAR_WAIT(mbar, ph1); ph1 ^= 1; }
        else     { MBAR_WAIT(mbar, ph0); ph0 ^= 1; }

        compute_tile((const float*)(smem + xoff), sw4, acc, wm, wn, lane);
        __syncthreads();                 // all warps done reading this buffer

        int nn = tile + 2 * GRID;        // refill this buffer for tile+2
        if (nn < TILES)
            load_x_bulk(X + (size_t)nn * BM * D, sbase + xoff, mbar, tid);

        store_tile(Y, tile, acc, wm, wn, lane);   // overlaps the bulk in flight
        buf ^= 1;
    }
}

// ---------------------------------------------------------------------------
extern "C" void kernel_launch(void* const* d_in, const int* in_sizes, int n_in,
                              void* d_out, int out_size) {
    const float* X = (const float*)d_in[0];  // [524288, 128]
    const float* W = (const float*)d_in[1];  // [16, 128, 128]
    const float* s = (const float*)d_in[2];  // [16, 1]
    float* Y = (float*)d_out;                // [524288, 128]

    prep_kernel<<<16, 256>>>(W, s);

    cudaFuncSetAttribute(gemm_kernel, cudaFuncAttributeMaxDynamicSharedMemorySize,
                         SM_TOTAL);
    gemm_kernel<<<GRID, NTHREADS, SM_TOTAL>>>(X, Y);
}

// round 16
// speedup vs baseline: 1.6876x; 1.2879x over previous
#include <cuda_runtime.h>
#include <cuda_fp16.h>
#include <cstdint>

// ---------------------------------------------------------------------------
// out[524288,128] = X @ (sum_r s_r W_r).  mma.sync m16n8k16 fp16 (fp32 accum).
// fp16 mantissa == tf32 mantissa (10 bits) -> same rounding as the measured
// tf32 kernels (rel_err 2.9e-4), but HALF the MMAs and HALF the operand LDS.
// R15 structure otherwise: 8 warps 4Mx2N, bulk-async X double buffer,
// persistent GRID=148, software-pipelined k loop.
// ---------------------------------------------------------------------------
#define NREL 16
#define D 128
#define NNODES 524288

#define BM 128
#define XSTRIDE 136                 // floats; 136 mod 32 == 8 -> LDS.64 conflict-free
#define XBUF_BYTES (BM * XSTRIDE * 4)   // 69632
#define TILES (NNODES / BM)         // 4096
#define GRID 148                    // persistent: 27-28 tiles per CTA
#define NTHREADS 256

// smem layout (byte offsets)
#define SM_MBAR_W 0
#define SM_MBAR0  8
#define SM_MBAR1  16
#define SM_W      1024              // 32 KB fp16 W fragments
#define SM_X0     (SM_W + 32768)
#define SM_X1     (SM_X0 + XBUF_BYTES)
#define SM_TOTAL  (SM_X1 + XBUF_BYTES)   // 173056 bytes

// W_eff in paired m16n8k16 fp16 B-fragment layout:
// entry ((ks*8 + q)*32 + lane) -> float4 of 4 half2:
//   {b0(n8=2q), b1(2q), b0(2q+1), b1(2q+1)} where for k-step ks, lane:
//   b0 = {W[ks*16 + (lane%4)*2][n], W[ks*16 + (lane%4)*2 + 1][n]}
//   b1 = {W[ks*16 + (lane%4)*2 + 8][n], W[.. + 9][n]},  n = n8*8 + lane/4
__device__ float4 g_wfragh[8 * 8 * 32];

__device__ __forceinline__ uint32_t smem_u32(const void* p) {
    uint32_t a;
    asm("{ .reg .u64 t; cvta.to.shared.u64 t, %1; cvt.u32.u64 %0, t; }" : "=r"(a) : "l"(p));
    return a;
}
__device__ __forceinline__ uint32_t pack_h2(float lo, float hi) {
    __half2 h = __floats2half2_rn(lo, hi);
    return *reinterpret_cast<uint32_t*>(&h);
}
__device__ __forceinline__ void bulk_ld(uint32_t dst, const void* src, uint32_t bytes,
                                        uint32_t mbar) {
    asm volatile(
        "cp.async.bulk.shared::cluster.global.mbarrier::complete_tx::bytes [%0], [%1], %2, [%3];"
        :: "r"(dst), "l"(src), "r"(bytes), "r"(mbar) : "memory");
}
#define MBAR_INIT(m, n) \
    asm volatile("mbarrier.init.shared.b64 [%0], %1;" :: "r"(m), "r"((uint32_t)(n)) : "memory")
#define MBAR_EXPECT(m, tx) \
    asm volatile("mbarrier.arrive.expect_tx.shared.b64 _, [%0], %1;" :: "r"(m), "r"((uint32_t)(tx)) : "memory")
#define MBAR_WAIT(m, parity) do {                                                \
    uint32_t _m = (m), _p = (parity), _d;                                        \
    asm volatile("{ .reg .pred p; mbarrier.try_wait.parity.acquire.cta.shared::cta.b64 p, [%1], %2; selp.b32 %0,1,0,p; }" \
                 : "=r"(_d) : "r"(_m), "r"(_p) : "memory");                      \
    if (!_d) {                                                                   \
        asm volatile("{ .reg .pred P1; WL_%=: mbarrier.try_wait.parity.acquire.cta.shared::cta.b64 P1, [%0], %1, 0x989680;" \
                     " @P1 bra.uni WD_%=; bra.uni WL_%=; WD_%=: }"               \
                     :: "r"(_m), "r"(_p) : "memory");                            \
    }                                                                            \
} while (0)

__device__ __forceinline__ void mma_f16(float* c, const uint32_t* a, uint32_t b0, uint32_t b1) {
    asm volatile(
        "mma.sync.aligned.m16n8k16.row.col.f32.f16.f16.f32 "
        "{%0,%1,%2,%3}, {%4,%5,%6,%7}, {%8,%9}, {%0,%1,%2,%3};\n"
        : "+f"(c[0]), "+f"(c[1]), "+f"(c[2]), "+f"(c[3])
        : "r"(a[0]), "r"(a[1]), "r"(a[2]), "r"(a[3]), "r"(b0), "r"(b1));
}

// ---------------------------------------------------------------------------
// Kernel 1: fold relations -> W_eff, fp16-round, store paired k16 B-fragments
// ---------------------------------------------------------------------------
__global__ void prep_kernel(const float* __restrict__ W, const float* __restrict__ s) {
    int idx  = blockIdx.x * 256 + threadIdx.x;   // 0..2047
    int lane = idx & 31;
    int q    = (idx >> 5) & 7;
    int ks   = idx >> 8;                          // 0..7

    int k0 = ks * 16 + (lane & 3) * 2;
    int n0 = (2 * q) * 8 + (lane >> 2);
    int n1 = n0 + 8;

    float a0 = 0.f, a1 = 0.f, a2 = 0.f, a3 = 0.f;   // n0: k0,k0+1,k0+8,k0+9
    float c0 = 0.f, c1 = 0.f, c2 = 0.f, c3 = 0.f;   // n1: same
#pragma unroll
    for (int r = 0; r < NREL; r++) {
        float sc = s[r];
        const float* wr = W + (size_t)r * D * D;
        a0 = fmaf(sc, wr[(k0    ) * D + n0], a0);
        a1 = fmaf(sc, wr[(k0 + 1) * D + n0], a1);
        a2 = fmaf(sc, wr[(k0 + 8) * D + n0], a2);
        a3 = fmaf(sc, wr[(k0 + 9) * D + n0], a3);
        c0 = fmaf(sc, wr[(k0    ) * D + n1], c0);
        c1 = fmaf(sc, wr[(k0 + 1) * D + n1], c1);
        c2 = fmaf(sc, wr[(k0 + 8) * D + n1], c2);
        c3 = fmaf(sc, wr[(k0 + 9) * D + n1], c3);
    }
    float4 v;
    v.x = __uint_as_float(pack_h2(a0, a1));   // b0(n0)
    v.y = __uint_as_float(pack_h2(a2, a3));   // b1(n0)
    v.z = __uint_as_float(pack_h2(c0, c1));   // b0(n1)
    v.w = __uint_as_float(pack_h2(c2, c3));   // b1(n1)
    g_wfragh[idx] = v;
}

// ---------------------------------------------------------------------------
// X tile loader: one 512B bulk per row (dst stride 544B keeps pad)
// ---------------------------------------------------------------------------
__device__ __forceinline__ void load_x_bulk(const float* __restrict__ gx,
                                            uint32_t sdst, uint32_t mbar, int tid) {
    if (tid == 0) MBAR_EXPECT(mbar, BM * D * 4);           // 65536 bytes
    if (tid < BM) bulk_ld(sdst + tid * (XSTRIDE * 4), gx + (size_t)tid * D, D * 4, mbar);
}

// ---------------------------------------------------------------------------
// k-step fragment loaders
// ---------------------------------------------------------------------------
__device__ __forceinline__ void load_a_frag(const float* __restrict__ xb,
                                            int wm, int lane, int ks, uint32_t a[2][4]) {
#pragma unroll
    for (int mf = 0; mf < 2; mf++) {
        const float* ap = xb + (wm * 32 + mf * 16 + (lane >> 2)) * XSTRIDE
                             + ks * 16 + (lane & 3) * 2;
        float2 v0 = *(const float2*)(ap);                    // rows g,   k0..k0+1
        float2 v1 = *(const float2*)(ap + 8 * XSTRIDE);      // rows g+8, k0..k0+1
        float2 v2 = *(const float2*)(ap + 8);                // rows g,   k0+8..9
        float2 v3 = *(const float2*)(ap + 8 * XSTRIDE + 8);  // rows g+8, k0+8..9
        a[mf][0] = pack_h2(v0.x, v0.y);
        a[mf][1] = pack_h2(v1.x, v1.y);
        a[mf][2] = pack_h2(v2.x, v2.y);
        a[mf][3] = pack_h2(v3.x, v3.y);
    }
}
__device__ __forceinline__ void load_b_frag(const float4* __restrict__ swh,
                                            int wn, int lane, int ks, float4 bv[4]) {
#pragma unroll
    for (int qq = 0; qq < 4; qq++)
        bv[qq] = swh[(ks * 8 + wn * 4 + qq) * 32 + lane];   // LDS.128
}
__device__ __forceinline__ void mma_step(float acc[2][8][4], uint32_t a[2][4], float4 bv[4]) {
#pragma unroll
    for (int qq = 0; qq < 4; qq++) {
        uint32_t b0a = __float_as_uint(bv[qq].x), b1a = __float_as_uint(bv[qq].y);
        uint32_t b0b = __float_as_uint(bv[qq].z), b1b = __float_as_uint(bv[qq].w);
#pragma unroll
        for (int mf = 0; mf < 2; mf++) {
            mma_f16(acc[mf][2 * qq + 0], a[mf], b0a, b1a);
            mma_f16(acc[mf][2 * qq + 1], a[mf], b0b, b1b);
        }
    }
}

// ---------------------------------------------------------------------------
// Per-tile compute: software-pipelined over 8 k16-steps
// ---------------------------------------------------------------------------
__device__ __forceinline__ void compute_tile(const float* __restrict__ xb,
                                             const float4* __restrict__ swh,
                                             float acc[2][8][4],
                                             int wm, int wn, int lane) {
#pragma unroll
    for (int mf = 0; mf < 2; mf++)
#pragma unroll
        for (int nf = 0; nf < 8; nf++)
#pragma unroll
            for (int q = 0; q < 4; q++) acc[mf][nf][q] = 0.f;

    uint32_t a0[2][4], a1[2][4];
    float4   b0v[4],  b1v[4];
    load_a_frag(xb, wm, lane, 0, a0);
    load_b_frag(swh, wn, lane, 0, b0v);

#pragma unroll
    for (int ks = 0; ks < 8; ks++) {
        if (ks + 1 < 8) {
            if (ks & 1) { load_a_frag(xb, wm, lane, ks + 1, a0);
                          load_b_frag(swh, wn, lane, ks + 1, b0v); }
            else        { load_a_frag(xb, wm, lane, ks + 1, a1);
                          load_b_frag(swh, wn, lane, ks + 1, b1v); }
        }
        if (ks & 1) mma_step(acc, a1, b1v);
        else        mma_step(acc, a0, b0v);
    }
}

__device__ __forceinline__ void store_tile(float* __restrict__ Y, int tile,
                                           const float acc[2][8][4],
                                           int wm, int wn, int lane) {
    float* yp = Y + (size_t)tile * BM * D;
#pragma unroll
    for (int mf = 0; mf < 2; mf++) {
        int row0 = wm * 32 + mf * 16 + (lane >> 2);
#pragma unroll
        for (int nf = 0; nf < 8; nf++) {
            int col = wn * 64 + nf * 8 + 2 * (lane & 3);
            float2 v0 = make_float2(acc[mf][nf][0], acc[mf][nf][1]);
            float2 v1 = make_float2(acc[mf][nf][2], acc[mf][nf][3]);
            *(float2*)(yp + (size_t)row0 * D + col)       = v0;
            *(float2*)(yp + (size_t)(row0 + 8) * D + col) = v1;
        }
    }
}

// ---------------------------------------------------------------------------
// Kernel 2: persistent grid-stride GEMM, bulk-async double buffer
// ---------------------------------------------------------------------------
__global__ void __launch_bounds__(NTHREADS, 1)
gemm_kernel(const float* __restrict__ X, float* __restrict__ Y) {
    extern __shared__ char smem[];
    const uint32_t sbase = smem_u32(smem);
    const float4* swh = (const float4*)(smem + SM_W);

    const int tid  = threadIdx.x;
    const int warp = tid >> 5;
    const int lane = tid & 31;
    const int wm   = warp >> 1;          // 0..3  (M groups of 32 rows)
    const int wn   = warp & 1;           // 0..1  (N groups of 64 cols)

    if (tid == 0) {
        MBAR_INIT(sbase + SM_MBAR_W, 1);
        MBAR_INIT(sbase + SM_MBAR0, 1);
        MBAR_INIT(sbase + SM_MBAR1, 1);
    }
    __syncthreads();

    // Prologue: W (one 32KB bulk), X tile 0, X tile 1
    if (tid == 0) {
        MBAR_EXPECT(sbase + SM_MBAR_W, 32768);
        bulk_ld(sbase + SM_W, g_wfragh, 32768, sbase + SM_MBAR_W);
    }
    int t0 = blockIdx.x;
    load_x_bulk(X + (size_t)t0 * BM * D, sbase + SM_X0, sbase + SM_MBAR0, tid);
    if (t0 + GRID < TILES)
        load_x_bulk(X + (size_t)(t0 + GRID) * BM * D, sbase + SM_X1, sbase + SM_MBAR1, tid);

    MBAR_WAIT(sbase + SM_MBAR_W, 0);     // W fragments ready

    int ph0 = 0, ph1 = 0;
    int buf = 0;
    float acc[2][8][4];

    for (int tile = t0; tile < TILES; tile += GRID) {
        uint32_t mbar = sbase + (buf ? SM_MBAR1 : SM_MBAR0);
        uint32_t xoff = buf ? SM_X1 : SM_X0;
        if (buf) { MBAR_WAIT(mbar, ph1); ph1 ^= 1; }
        else     { MBAR_WAIT(mbar, ph0); ph0 ^= 1; }

        compute_tile((const float*)(smem + xoff), swh, acc, wm, wn, lane);
        __syncthreads();                 // all warps done reading this buffer

        int nn = tile + 2 * GRID;        // refill this buffer for tile+2
        if (nn < TILES)
            load_x_bulk(X + (size_t)nn * BM * D, sbase + xoff, mbar, tid);

        store_tile(Y, tile, acc, wm, wn, lane);   // overlaps the bulk in flight
        buf ^= 1;
    }
}

// ---------------------------------------------------------------------------
extern "C" void kernel_launch(void* const* d_in, const int* in_sizes, int n_in,
                              void* d_out, int out_size) {
    const float* X = (const float*)d_in[0];  // [524288, 128]
    const float* W = (const float*)d_in[1];  // [16, 128, 128]
    const float* s = (const float*)d_in[2];  // [16, 1]
    float* Y = (float*)d_out;                // [524288, 128]

    prep_kernel<<<8, 256>>>(W, s);

    cudaFuncSetAttribute(gemm_kernel, cudaFuncAttributeMaxDynamicSharedMemorySize,
                         SM_TOTAL);
    gemm_kernel<<<GRID, NTHREADS, SM_TOTAL>>>(X, Y);
}

// round 17
// speedup vs baseline: 1.7863x; 1.0585x over previous
#include <cuda_runtime.h>
#include <cuda_fp16.h>
#include <cstdint>

// ---------------------------------------------------------------------------
// out[524288,128] = X @ (sum_r s_r W_r).  mma.sync m16n8k16 fp16 (fp32 accum).
// R16 +: ALL B fragments in registers (128/thread, loaded once) -> zero B LDS
// in the loop; W smem region reused as a 3rd X buffer (3-deep TMA pipeline).
// ---------------------------------------------------------------------------
#define NREL 16
#define D 128
#define NNODES 524288

#define BM 128
#define XSTRIDE 136                 // floats; 136 mod 32 == 8 -> LDS.64 conflict-free
#define XBUF_BYTES (BM * XSTRIDE * 4)   // 69632
#define TILES (NNODES / BM)         // 4096
#define GRID 148                    // persistent: 27-28 tiles per CTA
#define NTHREADS 256

// smem layout (byte offsets): 4 mbarriers, then 3 X buffers.
// W fragment image (32 KB) is staged into the X2 region, consumed into
// registers, then X2 is recycled as the third X buffer.
#define SM_MBAR_W 0
#define SM_MBAR0  8
#define SM_MBAR1  16
#define SM_MBAR2  24
#define SM_X0     1024
#define SM_X1     (SM_X0 + XBUF_BYTES)
#define SM_X2     (SM_X1 + XBUF_BYTES)
#define SM_TOTAL  (SM_X2 + XBUF_BYTES)   // 209920 bytes

// W_eff in paired m16n8k16 fp16 B-fragment layout:
// entry ((ks*8 + q)*32 + lane) -> float4 of 4 half2:
//   {b0(n8=2q), b1(2q), b0(2q+1), b1(2q+1)}, n = n8*8 + lane/4,
//   b0 = {W[ks*16+(lane%4)*2][n], W[..+1][n]}, b1 = {W[..+8][n], W[..+9][n]}
__device__ float4 g_wfragh[8 * 8 * 32];

__device__ __forceinline__ uint32_t smem_u32(const void* p) {
    uint32_t a;
    asm("{ .reg .u64 t; cvta.to.shared.u64 t, %1; cvt.u32.u64 %0, t; }" : "=r"(a) : "l"(p));
    return a;
}
__device__ __forceinline__ uint32_t pack_h2(float lo, float hi) {
    __half2 h = __floats2half2_rn(lo, hi);
    return *reinterpret_cast<uint32_t*>(&h);
}
__device__ __forceinline__ void bulk_ld(uint32_t dst, const void* src, uint32_t bytes,
                                        uint32_t mbar) {
    asm volatile(
        "cp.async.bulk.shared::cluster.global.mbarrier::complete_tx::bytes [%0], [%1], %2, [%3];"
        :: "r"(dst), "l"(src), "r"(bytes), "r"(mbar) : "memory");
}
#define MBAR_INIT(m, n) \
    asm volatile("mbarrier.init.shared.b64 [%0], %1;" :: "r"(m), "r"((uint32_t)(n)) : "memory")
#define MBAR_EXPECT(m, tx) \
    asm volatile("mbarrier.arrive.expect_tx.shared.b64 _, [%0], %1;" :: "r"(m), "r"((uint32_t)(tx)) : "memory")
#define MBAR_WAIT(m, parity) do {                                                \
    uint32_t _m = (m), _p = (parity), _d;                                        \
    asm volatile("{ .reg .pred p; mbarrier.try_wait.parity.acquire.cta.shared::cta.b64 p, [%1], %2; selp.b32 %0,1,0,p; }" \
                 : "=r"(_d) : "r"(_m), "r"(_p) : "memory");                      \
    if (!_d) {                                                                   \
        asm volatile("{ .reg .pred P1; WL_%=: mbarrier.try_wait.parity.acquire.cta.shared::cta.b64 P1, [%0], %1, 0x989680;" \
                     " @P1 bra.uni WD_%=; bra.uni WL_%=; WD_%=: }"               \
                     :: "r"(_m), "r"(_p) : "memory");                            \
    }                                                                            \
} while (0)

__device__ __forceinline__ void mma_f16(float* c, const uint32_t* a, uint32_t b0, uint32_t b1) {
    asm volatile(
        "mma.sync.aligned.m16n8k16.row.col.f32.f16.f16.f32 "
        "{%0,%1,%2,%3}, {%4,%5,%6,%7}, {%8,%9}, {%0,%1,%2,%3};\n"
        : "+f"(c[0]), "+f"(c[1]), "+f"(c[2]), "+f"(c[3])
        : "r"(a[0]), "r"(a[1]), "r"(a[2]), "r"(a[3]), "r"(b0), "r"(b1));
}

// ---------------------------------------------------------------------------
// Kernel 1: fold relations -> W_eff, fp16-round, store paired k16 B-fragments
// ---------------------------------------------------------------------------
__global__ void prep_kernel(const float* __restrict__ W, const float* __restrict__ s) {
    int idx  = blockIdx.x * 256 + threadIdx.x;   // 0..2047
    int lane = idx & 31;
    int q    = (idx >> 5) & 7;
    int ks   = idx >> 8;                          // 0..7

    int k0 = ks * 16 + (lane & 3) * 2;
    int n0 = (2 * q) * 8 + (lane >> 2);
    int n1 = n0 + 8;

    float a0 = 0.f, a1 = 0.f, a2 = 0.f, a3 = 0.f;
    float c0 = 0.f, c1 = 0.f, c2 = 0.f, c3 = 0.f;
#pragma unroll
    for (int r = 0; r < NREL; r++) {
        float sc = s[r];
        const float* wr = W + (size_t)r * D * D;
        a0 = fmaf(sc, wr[(k0    ) * D + n0], a0);
        a1 = fmaf(sc, wr[(k0 + 1) * D + n0], a1);
        a2 = fmaf(sc, wr[(k0 + 8) * D + n0], a2);
        a3 = fmaf(sc, wr[(k0 + 9) * D + n0], a3);
        c0 = fmaf(sc, wr[(k0    ) * D + n1], c0);
        c1 = fmaf(sc, wr[(k0 + 1) * D + n1], c1);
        c2 = fmaf(sc, wr[(k0 + 8) * D + n1], c2);
        c3 = fmaf(sc, wr[(k0 + 9) * D + n1], c3);
    }
    float4 v;
    v.x = __uint_as_float(pack_h2(a0, a1));
    v.y = __uint_as_float(pack_h2(a2, a3));
    v.z = __uint_as_float(pack_h2(c0, c1));
    v.w = __uint_as_float(pack_h2(c2, c3));
    g_wfragh[idx] = v;
}

// ---------------------------------------------------------------------------
// X tile loader: one 512B bulk per row (dst stride 544B keeps pad)
// ---------------------------------------------------------------------------
__device__ __forceinline__ void load_x_bulk(const float* __restrict__ gx,
                                            uint32_t sdst, uint32_t mbar, int tid) {
    if (tid == 0) MBAR_EXPECT(mbar, BM * D * 4);           // 65536 bytes
    if (tid < BM) bulk_ld(sdst + tid * (XSTRIDE * 4), gx + (size_t)tid * D, D * 4, mbar);
}

// ---------------------------------------------------------------------------
// A fragment loader (regs)
// ---------------------------------------------------------------------------
__device__ __forceinline__ void load_a_frag(const float* __restrict__ xb,
                                            int wm, int lane, int ks, uint32_t a[2][4]) {
#pragma unroll
    for (int mf = 0; mf < 2; mf++) {
        const float* ap = xb + (wm * 32 + mf * 16 + (lane >> 2)) * XSTRIDE
                             + ks * 16 + (lane & 3) * 2;
        float2 v0 = *(const float2*)(ap);
        float2 v1 = *(const float2*)(ap + 8 * XSTRIDE);
        float2 v2 = *(const float2*)(ap + 8);
        float2 v3 = *(const float2*)(ap + 8 * XSTRIDE + 8);
        a[mf][0] = pack_h2(v0.x, v0.y);
        a[mf][1] = pack_h2(v1.x, v1.y);
        a[mf][2] = pack_h2(v2.x, v2.y);
        a[mf][3] = pack_h2(v3.x, v3.y);
    }
}

// ---------------------------------------------------------------------------
// Per-tile compute: B entirely in registers, A software-pipelined over 8 ks
// ---------------------------------------------------------------------------
__device__ __forceinline__ void compute_tile(const float* __restrict__ xb,
                                             const float4 breg[8][4],
                                             float acc[2][8][4],
                                             int wm, int lane) {
#pragma unroll
    for (int mf = 0; mf < 2; mf++)
#pragma unroll
        for (int nf = 0; nf < 8; nf++)
#pragma unroll
            for (int q = 0; q < 4; q++) acc[mf][nf][q] = 0.f;

    uint32_t a0[2][4], a1[2][4];
    load_a_frag(xb, wm, lane, 0, a0);

#pragma unroll
    for (int ks = 0; ks < 8; ks++) {
        if (ks + 1 < 8) {
            if (ks & 1) load_a_frag(xb, wm, lane, ks + 1, a0);
            else        load_a_frag(xb, wm, lane, ks + 1, a1);
        }
        uint32_t (*a)[4] = (ks & 1) ? a1 : a0;
#pragma unroll
        for (int qq = 0; qq < 4; qq++) {
            uint32_t b0a = __float_as_uint(breg[ks][qq].x);
            uint32_t b1a = __float_as_uint(breg[ks][qq].y);
            uint32_t b0b = __float_as_uint(breg[ks][qq].z);
            uint32_t b1b = __float_as_uint(breg[ks][qq].w);
#pragma unroll
            for (int mf = 0; mf < 2; mf++) {
                mma_f16(acc[mf][2 * qq + 0], a[mf], b0a, b1a);
                mma_f16(acc[mf][2 * qq + 1], a[mf], b0b, b1b);
            }
        }
    }
}

__device__ __forceinline__ void store_tile(float* __restrict__ Y, int tile,
                                           const float acc[2][8][4],
                                           int wm, int wn, int lane) {
    float* yp = Y + (size_t)tile * BM * D;
#pragma unroll
    for (int mf = 0; mf < 2; mf++) {
        int row0 = wm * 32 + mf * 16 + (lane >> 2);
#pragma unroll
        for (int nf = 0; nf < 8; nf++) {
            int col = wn * 64 + nf * 8 + 2 * (lane & 3);
            float2 v0 = make_float2(acc[mf][nf][0], acc[mf][nf][1]);
            float2 v1 = make_float2(acc[mf][nf][2], acc[mf][nf][3]);
            *(float2*)(yp + (size_t)row0 * D + col)       = v0;
            *(float2*)(yp + (size_t)(row0 + 8) * D + col) = v1;
        }
    }
}

// ---------------------------------------------------------------------------
// Kernel 2: persistent GEMM, 3-stage bulk-async X pipeline, B in registers
// ---------------------------------------------------------------------------
__global__ void __launch_bounds__(NTHREADS, 1)
gemm_kernel(const float* __restrict__ X, float* __restrict__ Y) {
    extern __shared__ char smem[];
    const uint32_t sbase = smem_u32(smem);

    const int tid  = threadIdx.x;
    const int warp = tid >> 5;
    const int lane = tid & 31;
    const int wm   = warp >> 1;          // 0..3  (M groups of 32 rows)
    const int wn   = warp & 1;           // 0..1  (N groups of 64 cols)

    if (tid == 0) {
        MBAR_INIT(sbase + SM_MBAR_W, 1);
        MBAR_INIT(sbase + SM_MBAR0, 1);
        MBAR_INIT(sbase + SM_MBAR1, 1);
        MBAR_INIT(sbase + SM_MBAR2, 1);
    }
    __syncthreads();

    // Prologue: W image into X2 region; X tiles 0,1 into X0,X1
    if (tid == 0) {
        MBAR_EXPECT(sbase + SM_MBAR_W, 32768);
        bulk_ld(sbase + SM_X2, g_wfragh, 32768, sbase + SM_MBAR_W);
    }
    const int t0 = blockIdx.x;
    load_x_bulk(X + (size_t)t0 * BM * D, sbase + SM_X0, sbase + SM_MBAR0, tid);
    load_x_bulk(X + (size_t)(t0 + GRID) * BM * D, sbase + SM_X1, sbase + SM_MBAR1, tid);

    // B fragments -> registers (once), then recycle X2 as third buffer
    MBAR_WAIT(sbase + SM_MBAR_W, 0);
    float4 breg[8][4];
    {
        const float4* swh = (const float4*)(smem + SM_X2);
#pragma unroll
        for (int ks = 0; ks < 8; ks++)
#pragma unroll
            for (int qq = 0; qq < 4; qq++)
                breg[ks][qq] = swh[(ks * 8 + wn * 4 + qq) * 32 + lane];
    }
    __syncthreads();                     // all threads done reading W image
    load_x_bulk(X + (size_t)(t0 + 2 * GRID) * BM * D, sbase + SM_X2, sbase + SM_MBAR2, tid);

    int ph0 = 0, ph1 = 0, ph2 = 0;
    int buf = 0;
    float acc[2][8][4];

    for (int tile = t0; tile < TILES; tile += GRID) {
        uint32_t mbar, xoff;
        if      (buf == 0) { mbar = sbase + SM_MBAR0; xoff = SM_X0; MBAR_WAIT(mbar, ph0); ph0 ^= 1; }
        else if (buf == 1) { mbar = sbase + SM_MBAR1; xoff = SM_X1; MBAR_WAIT(mbar, ph1); ph1 ^= 1; }
        else               { mbar = sbase + SM_MBAR2; xoff = SM_X2; MBAR_WAIT(mbar, ph2); ph2 ^= 1; }

        compute_tile((const float*)(smem + xoff), breg, acc, wm, lane);
        __syncthreads();                 // all warps done reading this buffer

        int nn = tile + 3 * GRID;        // refill this buffer for tile+3
        if (nn < TILES)
            load_x_bulk(X + (size_t)nn * BM * D, sbase + xoff, mbar, tid);

        store_tile(Y, tile, acc, wm, wn, lane);   // overlaps the bulk in flight
        buf = (buf == 2) ? 0 : buf + 1;
    }
}

// ---------------------------------------------------------------------------
extern "C" void kernel_launch(void* const* d_in, const int* in_sizes, int n_in,
                              void* d_out, int out_size) {
    const float* X = (const float*)d_in[0];  // [524288, 128]
    const float* W = (const float*)d_in[1];  // [16, 128, 128]
    const float* s = (const float*)d_in[2];  // [16, 1]
    float* Y = (float*)d_out;                // [524288, 128]

    prep_kernel<<<8, 256>>>(W, s);

    cudaFuncSetAttribute(gemm_kernel, cudaFuncAttributeMaxDynamicSharedMemorySize,
                         SM_TOTAL);
    gemm_kernel<<<GRID, NTHREADS, SM_TOTAL>>>(X, Y);
}